// round 15
// baseline (speedup 1.0000x reference)
#include <cuda_runtime.h>
#include <cuda_fp16.h>
#include <stdint.h>
#include <math.h>

// Problem constants
#define T_TOK 8192
#define H_DIM 2048
#define F_DIM 1408
#define E_NUM 8
#define F2    (2 * F_DIM)
#define FH    (F_DIM / 2)          // u32 (fp16 pairs) per F-major row
#define HH    (H_DIM / 2)          // u32 pairs per H-major row
#define HID_PAIRS ((long long)T_TOK * HH)
#define W1_PAIRS  ((long long)E_NUM * F2 * HH)
#define W2_PAIRS  ((long long)E_NUM * H_DIM * FH)

// Tiling
#define BK       64
#define RSTRIDE  144               // smem bytes/row: 64 fp16 (128B) + 16B pad
#define A_BYTES  (128 * RSTRIDE)   // 18432
#define B_BYTES  (256 * RSTRIDE)   // 36864
#define STAGE_B  (A_BYTES + B_BYTES)            // 55296
#define SMEM_TILES_OFF 1024
#define SMEM_TOTAL (SMEM_TILES_OFF + 3 * STAGE_B)   // 166912
#define NTHREADS 320               // 8 consumer warps + 2 producer warps

// Named barriers: full[s] = 1+s, empty[s] = 4+s
__device__ __forceinline__ void bar_sync(int id) {
    asm volatile("bar.sync %0, %1;" :: "r"(id), "r"(NTHREADS) : "memory");
}
__device__ __forceinline__ void bar_arrive(int id) {
    asm volatile("bar.arrive %0, %1;" :: "r"(id), "r"(NTHREADS) : "memory");
}

// ---------------------------------------------------------------------------
// Static device scratch
// ---------------------------------------------------------------------------
__device__ int   g_cnt[E_NUM];
__device__ int   g_tok[E_NUM * T_TOK];
__device__ float g_wgt[E_NUM * T_TOK];
__device__ __align__(16) unsigned g_act[(size_t)E_NUM * T_TOK * FH];   // fp16x2
__device__ __align__(16) unsigned g_hid16[HID_PAIRS];
__device__ __align__(16) unsigned g_w1_16[W1_PAIRS];
__device__ __align__(16) unsigned g_w2_16[W2_PAIRS];

// ---------------------------------------------------------------------------
// Helpers
// ---------------------------------------------------------------------------
__device__ __forceinline__ uint32_t smem_u32(const void* p) {
    uint32_t a;
    asm("{ .reg .u64 t; cvta.to.shared.u64 t, %1; cvt.u32.u64 %0, t; }"
        : "=r"(a) : "l"(p));
    return a;
}

__device__ __forceinline__ void ldm4(uint32_t* r, uint32_t addr) {
    asm volatile("ldmatrix.sync.aligned.m8n8.x4.shared.b16 {%0,%1,%2,%3}, [%4];"
                 : "=r"(r[0]), "=r"(r[1]), "=r"(r[2]), "=r"(r[3]) : "r"(addr));
}

__device__ __forceinline__ void mma_f16(float* c, const uint32_t* a,
                                        uint32_t b0, uint32_t b1) {
    asm volatile(
        "mma.sync.aligned.m16n8k16.row.col.f32.f16.f16.f32 "
        "{%0,%1,%2,%3}, {%4,%5,%6,%7}, {%8,%9}, {%0,%1,%2,%3};"
        : "+f"(c[0]), "+f"(c[1]), "+f"(c[2]), "+f"(c[3])
        : "r"(a[0]), "r"(a[1]), "r"(a[2]), "r"(a[3]), "r"(b0), "r"(b1));
}

__device__ __forceinline__ void cpa16(uint32_t saddr, const unsigned* gaddr) {
    asm volatile("cp.async.cg.shared.global [%0], [%1], 16;"
                 :: "r"(saddr), "l"(gaddr) : "memory");
}
#define CP_COMMIT() asm volatile("cp.async.commit_group;" ::: "memory")
#define CP_WAIT1()  asm volatile("cp.async.wait_group 1;" ::: "memory")
#define CP_WAIT0()  asm volatile("cp.async.wait_group 0;" ::: "memory")

// pack two fp32 -> fp16x2 (a0 in low half = even k)
__device__ __forceinline__ uint32_t f16pair(float a0, float a1) {
    uint32_t r;
    asm("cvt.rn.f16x2.f32 %0, %1, %2;" : "=r"(r) : "f"(a1), "f"(a0));
    return r;
}

// ---------------------------------------------------------------------------
// init / route (proven)
// ---------------------------------------------------------------------------
__global__ void init_kernel(float* __restrict__ out) {
    int idx = blockIdx.x * blockDim.x + threadIdx.x;
    if (idx < E_NUM) g_cnt[idx] = 0;
    const long long n = (long long)T_TOK * H_DIM;
    long long stride = (long long)gridDim.x * blockDim.x;
    for (long long i = idx; i < n; i += stride) out[i] = 0.0f;
}

__global__ void route_kernel(const float* __restrict__ logits) {
    int t = blockIdx.x * blockDim.x + threadIdx.x;
    if (t >= T_TOK) return;
    float l[E_NUM];
#pragma unroll
    for (int i = 0; i < E_NUM; i++) l[i] = logits[t * E_NUM + i];
    int i0 = 0; float v0 = l[0];
#pragma unroll
    for (int i = 1; i < E_NUM; i++) if (l[i] > v0) { v0 = l[i]; i0 = i; }
    int i1 = -1; float v1 = -3.402823466e+38f;
#pragma unroll
    for (int i = 0; i < E_NUM; i++) if (i != i0 && l[i] > v1) { v1 = l[i]; i1 = i; }
    float r  = expf(v1 - v0);
    float w0 = 1.0f / (1.0f + r);
    float w1 = r / (1.0f + r);
    int p0 = atomicAdd(&g_cnt[i0], 1);
    g_tok[i0 * T_TOK + p0] = t; g_wgt[i0 * T_TOK + p0] = w0;
    int p1 = atomicAdd(&g_cnt[i1], 1);
    g_tok[i1 * T_TOK + p1] = t; g_wgt[i1 * T_TOK + p1] = w1;
}

// ---------------------------------------------------------------------------
// fp32 -> fp16 pre-conversion (streaming)
// ---------------------------------------------------------------------------
__global__ void cvt_kernel(const float* __restrict__ src,
                           unsigned* __restrict__ dst, long long npairs) {
    long long i = (long long)blockIdx.x * blockDim.x + threadIdx.x;
    long long stride = (long long)gridDim.x * blockDim.x;
    for (; 2 * i < npairs; i += stride) {
        float4 v = *(const float4*)(src + i * 4);
        *(uint2*)(dst + i * 2) = make_uint2(f16pair(v.x, v.y), f16pair(v.z, v.w));
    }
}

// ---------------------------------------------------------------------------
// Consumer warp-MMA for one K-chunk. Per warp: 64(M) x 64(N), K=64, fp16.
// ---------------------------------------------------------------------------
__device__ __forceinline__ void compute_chunk(
    float acc[4][8][4], uint32_t aB, uint32_t bB)
{
#pragma unroll
    for (int ks = 0; ks < 4; ks++) {
        const uint32_t ko = ks * 32;
        uint32_t b[16];
#pragma unroll
        for (int t = 0; t < 4; t++) ldm4(b + 4 * t, bB + t * 16 * RSTRIDE + ko);
#pragma unroll
        for (int mf = 0; mf < 4; mf++) {
            uint32_t a4[4];
            ldm4(a4, aB + mf * 16 * RSTRIDE + ko);
#pragma unroll
            for (int nf = 0; nf < 8; nf++)
                mma_f16(acc[mf][nf], a4, b[2 * nf], b[2 * nf + 1]);
        }
    }
}

// Producer: cp.async one chunk (BK=64). A: 2 rows x 8 x 16B, B: 4 rows x 8 x 16B.
__device__ __forceinline__ void produce_chunk(
    uint32_t stg, int c,
    const unsigned* a0p, const unsigned* a1p, uint32_t a0s, uint32_t a1s,
    const unsigned* const* bpp, uint32_t b0s)
{
    const unsigned* s0 = a0p + c * 32;
    const unsigned* s1 = a1p + c * 32;
#pragma unroll
    for (int j = 0; j < 8; j++) cpa16(stg + a0s + j * 16, s0 + j * 4);
#pragma unroll
    for (int j = 0; j < 8; j++) cpa16(stg + a1s + j * 16, s1 + j * 4);
    const uint32_t bb = stg + A_BYTES + b0s;
#pragma unroll
    for (int q = 0; q < 4; q++) {
        const unsigned* bs = bpp[q] + c * 32;
#pragma unroll
        for (int j = 0; j < 8; j++)
            cpa16(bb + (uint32_t)q * RSTRIDE + j * 16, bs + j * 4);
    }
}

// Producer mainloop (shared by both GEMMs)
__device__ __forceinline__ void producer_loop(
    uint32_t tiles, int NC,
    const unsigned* pa0, const unsigned* pa1, uint32_t a0s, uint32_t a1s,
    const unsigned* const* pb, uint32_t b0s)
{
    produce_chunk(tiles, 0, pa0, pa1, a0s, a1s, pb, b0s);
    CP_COMMIT();
    for (int c = 1; c <= NC; c++) {
        if (c < NC) {
            if (c >= 3) bar_sync(4 + (c % 3));          // stage free?
            produce_chunk(tiles + (uint32_t)(c % 3) * STAGE_B, c,
                          pa0, pa1, a0s, a1s, pb, b0s);
            CP_COMMIT();
            CP_WAIT1();                                  // chunk c-1 landed
        } else {
            CP_WAIT0();                                  // last chunk landed
        }
        bar_arrive(1 + ((c - 1) % 3));                   // publish chunk c-1
    }
}

// ---------------------------------------------------------------------------
// GEMM1: [128 gathered tokens] x [128 gate + 128 up cols], K=2048
//   grid = (64, 11, 8), 320 threads (8 consumer + 2 producer warps)
// ---------------------------------------------------------------------------
__global__ __launch_bounds__(NTHREADS, 1)
void gemm1_mma() {
    const int e   = blockIdx.z;
    const int cnt = g_cnt[e];
    const int m0  = blockIdx.x * 128;
    if (m0 >= cnt) return;
    const int n0t = blockIdx.y * 128;

    extern __shared__ char smem[];
    const uint32_t sbase = smem_u32(smem);
    int* stok = (int*)smem;
    const uint32_t tiles = sbase + SMEM_TILES_OFF;

    const int tid  = threadIdx.x;
    const int lane = tid & 31;
    const int wid  = tid >> 5;
    const bool is_prod = (wid >= 8);

    if (tid < 128) {
        int i = m0 + tid;
        stok[tid] = (i < cnt) ? g_tok[e * T_TOK + i] : 0;
    }
    __syncthreads();

    const int NC = H_DIM / BK;   // 32

    if (is_prod) {
        const int pt = tid - 256;              // 0..63
        const int ra = pt * 2;
        const unsigned* pa0 = g_hid16 + (size_t)stok[ra] * HH;
        const unsigned* pa1 = g_hid16 + (size_t)stok[ra + 1] * HH;
        const uint32_t a0s = (uint32_t)(ra * RSTRIDE);
        const uint32_t a1s = (uint32_t)((ra + 1) * RSTRIDE);
        const unsigned* w1e = g_w1_16 + (size_t)e * F2 * HH;
        const unsigned* pb[4];
#pragma unroll
        for (int q = 0; q < 4; q++) {
            const int rb = pt * 4 + q;
            const int bj = (rb >> 3) & 7;
            const int fcol = n0t + (rb >> 6) * 32 + ((bj >> 1) * 8) + (rb & 7);
            const int grow = fcol + ((bj & 1) ? F_DIM : 0);
            pb[q] = w1e + (size_t)grow * HH;
        }
        const uint32_t b0s = (uint32_t)((pt * 4) * RSTRIDE);
        producer_loop(tiles, NC, pa0, pa1, a0s, a1s, pb, b0s);
        return;
    }

    // ---- consumer ----
    const int wrow = wid & 1;
    const int wcol = wid >> 1;
    const uint32_t a_loff = (uint32_t)((lane & 15) * RSTRIDE + (lane >> 4) * 16)
                          + (uint32_t)(wrow * 64) * RSTRIDE;
    const uint32_t b_loff = (uint32_t)(((lane & 7) + ((lane >> 4) & 1) * 8) * RSTRIDE
                                       + ((lane >> 3) & 1) * 16)
                          + (uint32_t)(wcol * 64) * RSTRIDE;

    float acc[4][8][4];
#pragma unroll
    for (int i = 0; i < 4; i++)
#pragma unroll
        for (int j = 0; j < 8; j++)
#pragma unroll
            for (int q = 0; q < 4; q++) acc[i][j][q] = 0.0f;

    for (int c = 0; c < NC; c++) {
        bar_sync(1 + (c % 3));
        const uint32_t rb = tiles + (uint32_t)(c % 3) * STAGE_B;
        compute_chunk(acc, rb + a_loff, rb + A_BYTES + b_loff);
        bar_arrive(4 + (c % 3));
    }

    // epilogue: silu(gate)*up -> g_act fp16 pairs (gate=even nf, up=odd nf)
    const int g   = lane >> 2;
    const int tig = lane & 3;
#pragma unroll
    for (int mf = 0; mf < 4; mf++) {
        const int r0 = wrow * 64 + mf * 16 + g;
        const int r1 = r0 + 8;
#pragma unroll
        for (int p = 0; p < 4; p++) {
            const int ci = ((n0t + wcol * 32 + p * 8) >> 1) + tig;
            if (m0 + r0 < cnt) {
                float g0 = acc[mf][2*p][0],   g1v = acc[mf][2*p][1];
                float u0 = acc[mf][2*p+1][0], u1  = acc[mf][2*p+1][1];
                float a0 = (g0 / (1.0f + expf(-g0))) * u0;
                float a1 = (g1v / (1.0f + expf(-g1v))) * u1;
                g_act[(size_t)(e * T_TOK + m0 + r0) * FH + ci] = f16pair(a0, a1);
            }
            if (m0 + r1 < cnt) {
                float g0 = acc[mf][2*p][2],   g1v = acc[mf][2*p][3];
                float u0 = acc[mf][2*p+1][2], u1  = acc[mf][2*p+1][3];
                float a0 = (g0 / (1.0f + expf(-g0))) * u0;
                float a1 = (g1v / (1.0f + expf(-g1v))) * u1;
                g_act[(size_t)(e * T_TOK + m0 + r1) * FH + ci] = f16pair(a0, a1);
            }
        }
    }
}

// ---------------------------------------------------------------------------
// GEMM2: [128 slots] x [256 H cols], K=1408; weighted atomic scatter into out
//   grid = (64, 8, 8), 320 threads
// ---------------------------------------------------------------------------
__global__ __launch_bounds__(NTHREADS, 1)
void gemm2_mma(float* __restrict__ out) {
    const int e   = blockIdx.z;
    const int cnt = g_cnt[e];
    const int m0  = blockIdx.x * 128;
    if (m0 >= cnt) return;
    const int n0  = blockIdx.y * 256;

    extern __shared__ char smem[];
    const uint32_t sbase = smem_u32(smem);
    int* stok = (int*)smem;
    const uint32_t tiles = sbase + SMEM_TILES_OFF;

    const int tid  = threadIdx.x;
    const int lane = tid & 31;
    const int wid  = tid >> 5;
    const bool is_prod = (wid >= 8);

    if (tid < 128) {
        int i = m0 + tid;
        stok[tid] = (i < cnt) ? g_tok[e * T_TOK + i] : 0;
    }
    __syncthreads();

    const int NC = F_DIM / BK;   // 22

    if (is_prod) {
        const int pt = tid - 256;
        const int ra = pt * 2;
        const unsigned* pa0 = g_act + (size_t)(e * T_TOK + m0 + ra) * FH;
        const unsigned* pa1 = g_act + (size_t)(e * T_TOK + m0 + ra + 1) * FH;
        const uint32_t a0s = (uint32_t)(ra * RSTRIDE);
        const uint32_t a1s = (uint32_t)((ra + 1) * RSTRIDE);
        const unsigned* w2e = g_w2_16 + (size_t)e * H_DIM * FH;
        const unsigned* pb[4];
#pragma unroll
        for (int q = 0; q < 4; q++)
            pb[q] = w2e + (size_t)(n0 + pt * 4 + q) * FH;
        const uint32_t b0s = (uint32_t)((pt * 4) * RSTRIDE);
        producer_loop(tiles, NC, pa0, pa1, a0s, a1s, pb, b0s);
        return;
    }

    const int wrow = wid & 1;
    const int wcol = wid >> 1;
    const uint32_t a_loff = (uint32_t)((lane & 15) * RSTRIDE + (lane >> 4) * 16)
                          + (uint32_t)(wrow * 64) * RSTRIDE;
    const uint32_t b_loff = (uint32_t)(((lane & 7) + ((lane >> 4) & 1) * 8) * RSTRIDE
                                       + ((lane >> 3) & 1) * 16)
                          + (uint32_t)(wcol * 64) * RSTRIDE;

    float acc[4][8][4];
#pragma unroll
    for (int i = 0; i < 4; i++)
#pragma unroll
        for (int j = 0; j < 8; j++)
#pragma unroll
            for (int q = 0; q < 4; q++) acc[i][j][q] = 0.0f;

    for (int c = 0; c < NC; c++) {
        bar_sync(1 + (c % 3));
        const uint32_t rb = tiles + (uint32_t)(c % 3) * STAGE_B;
        compute_chunk(acc, rb + a_loff, rb + A_BYTES + b_loff);
        bar_arrive(4 + (c % 3));
    }

    // epilogue: out[token] += w * y (exactly 2 atomics per element across grid)
    const int g   = lane >> 2;
    const int tig = lane & 3;
#pragma unroll
    for (int mf = 0; mf < 4; mf++) {
        const int r0 = wrow * 64 + mf * 16 + g;
        const int r1 = r0 + 8;
        const bool v0 = (m0 + r0) < cnt;
        const bool v1 = (m0 + r1) < cnt;
        const float w0 = v0 ? g_wgt[e * T_TOK + m0 + r0] : 0.0f;
        const float w1 = v1 ? g_wgt[e * T_TOK + m0 + r1] : 0.0f;
        float* o0 = out + (size_t)stok[r0] * H_DIM;
        float* o1 = out + (size_t)stok[r1] * H_DIM;
#pragma unroll
        for (int nf = 0; nf < 8; nf++) {
            const int col = n0 + wcol * 64 + nf * 8 + 2 * tig;
            if (v0) {
                atomicAdd(o0 + col,     w0 * acc[mf][nf][0]);
                atomicAdd(o0 + col + 1, w0 * acc[mf][nf][1]);
            }
            if (v1) {
                atomicAdd(o1 + col,     w1 * acc[mf][nf][2]);
                atomicAdd(o1 + col + 1, w1 * acc[mf][nf][3]);
            }
        }
    }
}

// ---------------------------------------------------------------------------
// Launch
// ---------------------------------------------------------------------------
extern "C" void kernel_launch(void* const* d_in, const int* in_sizes, int n_in,
                              void* d_out, int out_size) {
    (void)in_sizes; (void)n_in; (void)out_size;
    const float* hidden = (const float*)d_in[0];
    const float* logits = (const float*)d_in[1];
    const float* w1     = (const float*)d_in[2];
    const float* w2     = (const float*)d_in[3];
    float*       out    = (float*)d_out;

    cudaFuncSetAttribute(gemm1_mma, cudaFuncAttributeMaxDynamicSharedMemorySize, SMEM_TOTAL);
    cudaFuncSetAttribute(gemm2_mma, cudaFuncAttributeMaxDynamicSharedMemorySize, SMEM_TOTAL);

    unsigned *hh, *w1h, *w2h;
    cudaGetSymbolAddress((void**)&hh,  g_hid16);
    cudaGetSymbolAddress((void**)&w1h, g_w1_16);
    cudaGetSymbolAddress((void**)&w2h, g_w2_16);

    init_kernel<<<2048, 256>>>(out);
    route_kernel<<<T_TOK / 256, 256>>>(logits);

    cvt_kernel<<<4096, 256>>>(hidden, hh,  HID_PAIRS);
    cvt_kernel<<<8192, 256>>>(w1,     w1h, W1_PAIRS);
    cvt_kernel<<<8192, 256>>>(w2,     w2h, W2_PAIRS);

    dim3 g1(T_TOK / 128, F_DIM / 128, E_NUM);   // (64, 11, 8)
    gemm1_mma<<<g1, NTHREADS, SMEM_TOTAL>>>();

    dim3 g2(T_TOK / 128, H_DIM / 256, E_NUM);   // (64, 8, 8)
    gemm2_mma<<<g2, NTHREADS, SMEM_TOTAL>>>(out);
}

// round 16
// speedup vs baseline: 1.0621x; 1.0621x over previous
#include <cuda_runtime.h>
#include <cuda_fp16.h>
#include <stdint.h>
#include <math.h>

// Problem constants
#define T_TOK 8192
#define H_DIM 2048
#define F_DIM 1408
#define E_NUM 8
#define F2    (2 * F_DIM)
#define FH    (F_DIM / 2)          // u32 (fp16 pairs) per F-major row
#define HH    (H_DIM / 2)          // u32 pairs per H-major row
#define HID_PAIRS ((long long)T_TOK * HH)
#define W1_PAIRS  ((long long)E_NUM * F2 * HH)
#define W2_PAIRS  ((long long)E_NUM * H_DIM * FH)

// Tiling
#define BK       32
#define RSTRIDE  80                // smem bytes/row: 32 fp16 (64B) + 16B pad
#define A_BYTES  (128 * RSTRIDE)   // 10240
#define B_BYTES  (256 * RSTRIDE)   // 20480
#define STAGE_B  (A_BYTES + B_BYTES)            // 30720
#define SMEM_TILES_OFF 1024
#define SMEM_TOTAL (SMEM_TILES_OFF + 3 * STAGE_B)   // 93184
#define NTHREADS 576               // 16 consumer warps + 2 producer warps

// ---------------------------------------------------------------------------
// Static device scratch
// ---------------------------------------------------------------------------
__device__ int   g_cnt[E_NUM];
__device__ int   g_tok[E_NUM * T_TOK];
__device__ float g_wgt[E_NUM * T_TOK];
__device__ __align__(16) unsigned g_act[(size_t)E_NUM * T_TOK * FH];   // fp16x2
__device__ __align__(16) unsigned g_hid16[HID_PAIRS];
__device__ __align__(16) unsigned g_w1_16[W1_PAIRS];
__device__ __align__(16) unsigned g_w2_16[W2_PAIRS];

// ---------------------------------------------------------------------------
// Helpers
// ---------------------------------------------------------------------------
__device__ __forceinline__ uint32_t smem_u32(const void* p) {
    uint32_t a;
    asm("{ .reg .u64 t; cvta.to.shared.u64 t, %1; cvt.u32.u64 %0, t; }"
        : "=r"(a) : "l"(p));
    return a;
}

__device__ __forceinline__ void ldm4(uint32_t* r, uint32_t addr) {
    asm volatile("ldmatrix.sync.aligned.m8n8.x4.shared.b16 {%0,%1,%2,%3}, [%4];"
                 : "=r"(r[0]), "=r"(r[1]), "=r"(r[2]), "=r"(r[3]) : "r"(addr));
}

__device__ __forceinline__ void mma_f16(float* c, const uint32_t* a,
                                        uint32_t b0, uint32_t b1) {
    asm volatile(
        "mma.sync.aligned.m16n8k16.row.col.f32.f16.f16.f32 "
        "{%0,%1,%2,%3}, {%4,%5,%6,%7}, {%8,%9}, {%0,%1,%2,%3};"
        : "+f"(c[0]), "+f"(c[1]), "+f"(c[2]), "+f"(c[3])
        : "r"(a[0]), "r"(a[1]), "r"(a[2]), "r"(a[3]), "r"(b0), "r"(b1));
}

__device__ __forceinline__ void cpa16(uint32_t saddr, const unsigned* gaddr) {
    asm volatile("cp.async.cg.shared.global [%0], [%1], 16;"
                 :: "r"(saddr), "l"(gaddr) : "memory");
}
#define CP_COMMIT() asm volatile("cp.async.commit_group;" ::: "memory")
#define CP_WAIT1()  asm volatile("cp.async.wait_group 1;" ::: "memory")

// pack two fp32 -> fp16x2 (a0 in low half = even k)
__device__ __forceinline__ uint32_t f16pair(float a0, float a1) {
    uint32_t r;
    asm("cvt.rn.f16x2.f32 %0, %1, %2;" : "=r"(r) : "f"(a1), "f"(a0));
    return r;
}

// ---------------------------------------------------------------------------
// init / route (proven)
// ---------------------------------------------------------------------------
__global__ void init_kernel(float* __restrict__ out) {
    int idx = blockIdx.x * blockDim.x + threadIdx.x;
    if (idx < E_NUM) g_cnt[idx] = 0;
    const long long n = (long long)T_TOK * H_DIM;
    long long stride = (long long)gridDim.x * blockDim.x;
    for (long long i = idx; i < n; i += stride) out[i] = 0.0f;
}

__global__ void route_kernel(const float* __restrict__ logits) {
    int t = blockIdx.x * blockDim.x + threadIdx.x;
    if (t >= T_TOK) return;
    float l[E_NUM];
#pragma unroll
    for (int i = 0; i < E_NUM; i++) l[i] = logits[t * E_NUM + i];
    int i0 = 0; float v0 = l[0];
#pragma unroll
    for (int i = 1; i < E_NUM; i++) if (l[i] > v0) { v0 = l[i]; i0 = i; }
    int i1 = -1; float v1 = -3.402823466e+38f;
#pragma unroll
    for (int i = 0; i < E_NUM; i++) if (i != i0 && l[i] > v1) { v1 = l[i]; i1 = i; }
    float r  = expf(v1 - v0);
    float w0 = 1.0f / (1.0f + r);
    float w1 = r / (1.0f + r);
    int p0 = atomicAdd(&g_cnt[i0], 1);
    g_tok[i0 * T_TOK + p0] = t; g_wgt[i0 * T_TOK + p0] = w0;
    int p1 = atomicAdd(&g_cnt[i1], 1);
    g_tok[i1 * T_TOK + p1] = t; g_wgt[i1 * T_TOK + p1] = w1;
}

// ---------------------------------------------------------------------------
// fp32 -> fp16 pre-conversion (streaming)
// ---------------------------------------------------------------------------
__global__ void cvt_kernel(const float* __restrict__ src,
                           unsigned* __restrict__ dst, long long npairs) {
    long long i = (long long)blockIdx.x * blockDim.x + threadIdx.x;
    long long stride = (long long)gridDim.x * blockDim.x;
    for (; 2 * i < npairs; i += stride) {
        float4 v = *(const float4*)(src + i * 4);
        *(uint2*)(dst + i * 2) = make_uint2(f16pair(v.x, v.y), f16pair(v.z, v.w));
    }
}

// ---------------------------------------------------------------------------
// Consumer warp-MMA for one K-chunk. Per warp: 64(M) x 32(N), K=32, fp16.
// ---------------------------------------------------------------------------
__device__ __forceinline__ void compute_chunk(
    float acc[4][4][4], uint32_t aB, uint32_t bB)
{
#pragma unroll
    for (int ks = 0; ks < 2; ks++) {
        const uint32_t ko = ks * 32;
        uint32_t b[8];
        ldm4(b,     bB + ko);
        ldm4(b + 4, bB + 16 * RSTRIDE + ko);
#pragma unroll
        for (int mf = 0; mf < 4; mf++) {
            uint32_t a4[4];
            ldm4(a4, aB + mf * 16 * RSTRIDE + ko);
#pragma unroll
            for (int nf = 0; nf < 4; nf++)
                mma_f16(acc[mf][nf], a4, b[2 * nf], b[2 * nf + 1]);
        }
    }
}

// Producer: cp.async one chunk. A: 2 rows x 2 x 16B, B: 4 rows x 2 x 16B.
__device__ __forceinline__ void produce_chunk(
    uint32_t stg, int c,
    const unsigned* a0p, const unsigned* a1p, uint32_t a0s, uint32_t a1s,
    const unsigned* const* bpp, uint32_t b0s)
{
    const unsigned* s0 = a0p + c * 16;
    const unsigned* s1 = a1p + c * 16;
#pragma unroll
    for (int j = 0; j < 4; j++) cpa16(stg + a0s + j * 16, s0 + j * 4);
#pragma unroll
    for (int j = 0; j < 4; j++) cpa16(stg + a1s + j * 16, s1 + j * 4);
    const uint32_t bb = stg + A_BYTES + b0s;
#pragma unroll
    for (int q = 0; q < 4; q++) {
        const unsigned* bs = bpp[q] + c * 16;
#pragma unroll
        for (int j = 0; j < 4; j++)
            cpa16(bb + (uint32_t)q * RSTRIDE + j * 16, bs + j * 4);
    }
}

// ---------------------------------------------------------------------------
// GEMM1: [128 gathered tokens] x [128 gate + 128 up cols], K=2048
//   grid = (64, 11, 8), 576 threads (16 consumer + 2 producer warps)
// ---------------------------------------------------------------------------
__global__ __launch_bounds__(NTHREADS, 1)
void gemm1_mma() {
    const int e   = blockIdx.z;
    const int cnt = g_cnt[e];
    const int m0  = blockIdx.x * 128;
    if (m0 >= cnt) return;
    const int n0t = blockIdx.y * 128;

    extern __shared__ char smem[];
    const uint32_t sbase = smem_u32(smem);
    int* stok = (int*)smem;
    const uint32_t tiles = sbase + SMEM_TILES_OFF;

    const int tid  = threadIdx.x;
    const int lane = tid & 31;
    const int wid  = tid >> 5;
    const bool is_prod = (wid >= 16);

    if (tid < 128) {
        int i = m0 + tid;
        stok[tid] = (i < cnt) ? g_tok[e * T_TOK + i] : 0;
    }
    __syncthreads();

    // ---- producer setup ----
    const unsigned *pa0 = 0, *pa1 = 0;
    const unsigned* pb[4] = {0, 0, 0, 0};
    uint32_t a0s = 0, a1s = 0, b0s = 0;
    if (is_prod) {
        const int pt = tid - 512;              // 0..63
        const int ra = pt * 2;
        pa0 = g_hid16 + (size_t)stok[ra] * HH;
        pa1 = g_hid16 + (size_t)stok[ra + 1] * HH;
        a0s = (uint32_t)(ra * RSTRIDE);
        a1s = (uint32_t)((ra + 1) * RSTRIDE);
        const unsigned* w1e = g_w1_16 + (size_t)e * F2 * HH;
#pragma unroll
        for (int q = 0; q < 4; q++) {
            const int rb = pt * 4 + q;
            const int bj = (rb >> 3) & 7;
            const int fcol = n0t + (rb >> 6) * 32 + ((bj >> 1) * 8) + (rb & 7);
            const int grow = fcol + ((bj & 1) ? F_DIM : 0);
            pb[q] = w1e + (size_t)grow * HH;
        }
        b0s = (uint32_t)((pt * 4) * RSTRIDE);
        produce_chunk(tiles, 0, pa0, pa1, a0s, a1s, pb, b0s); CP_COMMIT();
        produce_chunk(tiles + STAGE_B, 1, pa0, pa1, a0s, a1s, pb, b0s); CP_COMMIT();
        CP_WAIT1();   // chunk 0 complete
    }

    // ---- consumer setup ----
    const int wrow = wid & 1;          // 0..1 -> M offset
    const int wcol = wid >> 1;         // 0..7 -> 32 B-rows each
    const uint32_t a_loff = (uint32_t)((lane & 15) * RSTRIDE + (lane >> 4) * 16)
                          + (uint32_t)(wrow * 64) * RSTRIDE;
    const uint32_t b_loff = (uint32_t)(((lane & 7) + ((lane >> 4) & 1) * 8) * RSTRIDE
                                       + ((lane >> 3) & 1) * 16)
                          + (uint32_t)(wcol * 32) * RSTRIDE;

    float acc[4][4][4];
#pragma unroll
    for (int i = 0; i < 4; i++)
#pragma unroll
        for (int j = 0; j < 4; j++)
#pragma unroll
            for (int q = 0; q < 4; q++) acc[i][j][q] = 0.0f;

    __syncthreads();

    const int NC = H_DIM / BK;   // 64
    for (int c = 0; c < NC; c++) {
        if (is_prod) {
            if (c + 2 < NC)
                produce_chunk(tiles + (uint32_t)((c + 2) % 3) * STAGE_B, c + 2,
                              pa0, pa1, a0s, a1s, pb, b0s);
            CP_COMMIT();
            CP_WAIT1();   // chunk c+1 complete before next iteration
        } else {
            const uint32_t rb = tiles + (uint32_t)(c % 3) * STAGE_B;
            compute_chunk(acc, rb + a_loff, rb + A_BYTES + b_loff);
        }
        __syncthreads();
    }

    if (is_prod) return;

    // epilogue: silu(gate)*up -> g_act fp16 pairs
    // warp covers f-cols [n0t + wcol*16, +16); nf pairs (2p=gate, 2p+1=up)
    const int g   = lane >> 2;
    const int tig = lane & 3;
#pragma unroll
    for (int mf = 0; mf < 4; mf++) {
        const int r0 = wrow * 64 + mf * 16 + g;
        const int r1 = r0 + 8;
#pragma unroll
        for (int p = 0; p < 2; p++) {
            const int ci = ((n0t + wcol * 16 + p * 8) >> 1) + tig;
            if (m0 + r0 < cnt) {
                float g0 = acc[mf][2*p][0],   g1v = acc[mf][2*p][1];
                float u0 = acc[mf][2*p+1][0], u1  = acc[mf][2*p+1][1];
                float a0 = (g0 / (1.0f + expf(-g0))) * u0;
                float a1 = (g1v / (1.0f + expf(-g1v))) * u1;
                g_act[(size_t)(e * T_TOK + m0 + r0) * FH + ci] = f16pair(a0, a1);
            }
            if (m0 + r1 < cnt) {
                float g0 = acc[mf][2*p][2],   g1v = acc[mf][2*p][3];
                float u0 = acc[mf][2*p+1][2], u1  = acc[mf][2*p+1][3];
                float a0 = (g0 / (1.0f + expf(-g0))) * u0;
                float a1 = (g1v / (1.0f + expf(-g1v))) * u1;
                g_act[(size_t)(e * T_TOK + m0 + r1) * FH + ci] = f16pair(a0, a1);
            }
        }
    }
}

// ---------------------------------------------------------------------------
// GEMM2: [128 slots] x [256 H cols], K=1408; weighted atomic scatter into out
//   grid = (64, 8, 8), 576 threads
// ---------------------------------------------------------------------------
__global__ __launch_bounds__(NTHREADS, 1)
void gemm2_mma(float* __restrict__ out) {
    const int e   = blockIdx.z;
    const int cnt = g_cnt[e];
    const int m0  = blockIdx.x * 128;
    if (m0 >= cnt) return;
    const int n0  = blockIdx.y * 256;

    extern __shared__ char smem[];
    const uint32_t sbase = smem_u32(smem);
    int* stok = (int*)smem;
    const uint32_t tiles = sbase + SMEM_TILES_OFF;

    const int tid  = threadIdx.x;
    const int lane = tid & 31;
    const int wid  = tid >> 5;
    const bool is_prod = (wid >= 16);

    if (tid < 128) {
        int i = m0 + tid;
        stok[tid] = (i < cnt) ? g_tok[e * T_TOK + i] : 0;
    }
    __syncthreads();

    // ---- producer setup ----
    const unsigned *pa0 = 0, *pa1 = 0;
    const unsigned* pb[4] = {0, 0, 0, 0};
    uint32_t a0s = 0, a1s = 0, b0s = 0;
    if (is_prod) {
        const int pt = tid - 512;
        const int ra = pt * 2;
        pa0 = g_act + (size_t)(e * T_TOK + m0 + ra) * FH;
        pa1 = g_act + (size_t)(e * T_TOK + m0 + ra + 1) * FH;
        a0s = (uint32_t)(ra * RSTRIDE);
        a1s = (uint32_t)((ra + 1) * RSTRIDE);
        const unsigned* w2e = g_w2_16 + (size_t)e * H_DIM * FH;
#pragma unroll
        for (int q = 0; q < 4; q++)
            pb[q] = w2e + (size_t)(n0 + pt * 4 + q) * FH;
        b0s = (uint32_t)((pt * 4) * RSTRIDE);
        produce_chunk(tiles, 0, pa0, pa1, a0s, a1s, pb, b0s); CP_COMMIT();
        produce_chunk(tiles + STAGE_B, 1, pa0, pa1, a0s, a1s, pb, b0s); CP_COMMIT();
        CP_WAIT1();
    }

    const int wrow = wid & 1;
    const int wcol = wid >> 1;
    const uint32_t a_loff = (uint32_t)((lane & 15) * RSTRIDE + (lane >> 4) * 16)
                          + (uint32_t)(wrow * 64) * RSTRIDE;
    const uint32_t b_loff = (uint32_t)(((lane & 7) + ((lane >> 4) & 1) * 8) * RSTRIDE
                                       + ((lane >> 3) & 1) * 16)
                          + (uint32_t)(wcol * 32) * RSTRIDE;

    float acc[4][4][4];
#pragma unroll
    for (int i = 0; i < 4; i++)
#pragma unroll
        for (int j = 0; j < 4; j++)
#pragma unroll
            for (int q = 0; q < 4; q++) acc[i][j][q] = 0.0f;

    __syncthreads();

    const int NC = F_DIM / BK;   // 44
    for (int c = 0; c < NC; c++) {
        if (is_prod) {
            if (c + 2 < NC)
                produce_chunk(tiles + (uint32_t)((c + 2) % 3) * STAGE_B, c + 2,
                              pa0, pa1, a0s, a1s, pb, b0s);
            CP_COMMIT();
            CP_WAIT1();
        } else {
            const uint32_t rb = tiles + (uint32_t)(c % 3) * STAGE_B;
            compute_chunk(acc, rb + a_loff, rb + A_BYTES + b_loff);
        }
        __syncthreads();
    }

    if (is_prod) return;

    // epilogue: out[token] += w * y (exactly 2 atomics per element across grid)
    const int g   = lane >> 2;
    const int tig = lane & 3;
#pragma unroll
    for (int mf = 0; mf < 4; mf++) {
        const int r0 = wrow * 64 + mf * 16 + g;
        const int r1 = r0 + 8;
        const bool v0 = (m0 + r0) < cnt;
        const bool v1 = (m0 + r1) < cnt;
        const float w0 = v0 ? g_wgt[e * T_TOK + m0 + r0] : 0.0f;
        const float w1 = v1 ? g_wgt[e * T_TOK + m0 + r1] : 0.0f;
        float* o0 = out + (size_t)stok[r0] * H_DIM;
        float* o1 = out + (size_t)stok[r1] * H_DIM;
#pragma unroll
        for (int nf = 0; nf < 4; nf++) {
            const int col = n0 + wcol * 32 + nf * 8 + 2 * tig;
            if (v0) {
                atomicAdd(o0 + col,     w0 * acc[mf][nf][0]);
                atomicAdd(o0 + col + 1, w0 * acc[mf][nf][1]);
            }
            if (v1) {
                atomicAdd(o1 + col,     w1 * acc[mf][nf][2]);
                atomicAdd(o1 + col + 1, w1 * acc[mf][nf][3]);
            }
        }
    }
}

// ---------------------------------------------------------------------------
// Launch
// ---------------------------------------------------------------------------
extern "C" void kernel_launch(void* const* d_in, const int* in_sizes, int n_in,
                              void* d_out, int out_size) {
    (void)in_sizes; (void)n_in; (void)out_size;
    const float* hidden = (const float*)d_in[0];
    const float* logits = (const float*)d_in[1];
    const float* w1     = (const float*)d_in[2];
    const float* w2     = (const float*)d_in[3];
    float*       out    = (float*)d_out;

    cudaFuncSetAttribute(gemm1_mma, cudaFuncAttributeMaxDynamicSharedMemorySize, SMEM_TOTAL);
    cudaFuncSetAttribute(gemm2_mma, cudaFuncAttributeMaxDynamicSharedMemorySize, SMEM_TOTAL);

    unsigned *hh, *w1h, *w2h;
    cudaGetSymbolAddress((void**)&hh,  g_hid16);
    cudaGetSymbolAddress((void**)&w1h, g_w1_16);
    cudaGetSymbolAddress((void**)&w2h, g_w2_16);

    init_kernel<<<2048, 256>>>(out);
    route_kernel<<<T_TOK / 256, 256>>>(logits);

    cvt_kernel<<<4096, 256>>>(hidden, hh,  HID_PAIRS);
    cvt_kernel<<<8192, 256>>>(w1,     w1h, W1_PAIRS);
    cvt_kernel<<<8192, 256>>>(w2,     w2h, W2_PAIRS);

    dim3 g1(T_TOK / 128, F_DIM / 128, E_NUM);   // (64, 11, 8)
    gemm1_mma<<<g1, NTHREADS, SMEM_TOTAL>>>();

    dim3 g2(T_TOK / 128, H_DIM / 256, E_NUM);   // (64, 8, 8)
    gemm2_mma<<<g2, NTHREADS, SMEM_TOTAL>>>(out);
}